// round 2
// baseline (speedup 1.0000x reference)
#include <cuda_runtime.h>
#include <cstdint>

#define BATCH 16
#define NQ 2048
#define NK 2048
#define DHEAD 128
#define KBLOCKS 16                 // NK / 128
#define INV_SQRT_SCALE 0.08838834764831845f  // 1/sqrt(128)

// Deterministic per-(row, k-block) partial softmax denominators.
__device__ float g_partial[(size_t)BATCH * NQ * KBLOCKS];
// Mask storage mode: 0 = 1-byte bool, 1 = int32, 2 = float32.
__device__ int g_mask_mode;

// ---------------------------------------------------------------------------
// Detect how the boolean mask was widened by the harness. Deterministic.
// ---------------------------------------------------------------------------
__global__ void detect_mask_kernel(const unsigned char* __restrict__ m)
{
    int mode = 1;  // default: int32 (nonzero bytes only at pos%4==0)
    for (int i = 0; i < 4096; i++) {
        const unsigned char b = m[i];
        if (b != 0) {
            const int r = i & 3;
            if (r == 3 && b == 0x3F) { mode = 2; break; }  // float32 1.0f
            if (r != 0)              { mode = 0; break; }  // raw bytes
        }
    }
    g_mask_mode = mode;
}

// ---------------------------------------------------------------------------
// Kernel 1: E = exp(QK^T / sqrt(scale)) with mask -> 0. Writes unnormalized E
// into the att output region and partial row sums into g_partial.
// CTA tile: 128 q-rows x 128 keys, full D=128 reduction in chunks of 32.
// ---------------------------------------------------------------------------
__global__ __launch_bounds__(256) void qk_exp_kernel(
    const float* __restrict__ q,
    const float* __restrict__ k,
    const void* __restrict__ mask,
    float* __restrict__ att)
{
    const int b  = blockIdx.z;
    const int q0 = blockIdx.y * 128;
    const int k0 = blockIdx.x * 128;

    __shared__ __align__(16) float Qs[32][132];  // [d-within-chunk][row]
    __shared__ __align__(16) float Ks[32][132];  // [d-within-chunk][key]

    const int tid = threadIdx.x;
    const int tx = tid & 15;          // 0..15  -> key sub-tile
    const int ty = tid >> 4;          // 0..15  -> row sub-tile

    float acc[8][8];
#pragma unroll
    for (int i = 0; i < 8; i++)
#pragma unroll
        for (int j = 0; j < 8; j++) acc[i][j] = 0.0f;

    const float* qbase = q + ((size_t)b * NQ + q0) * DHEAD;
    const float* kbase = k + ((size_t)b * NK + k0) * DHEAD;

    for (int d0 = 0; d0 < DHEAD; d0 += 32) {
        // Load 128x32 chunks of Q and K, transposed into smem.
#pragma unroll
        for (int it = 0; it < 4; it++) {
            const int li  = it * 256 + tid;   // 0..1023
            const int d4  = li & 7;           // float4 index within 32 dims
            const int row = li >> 3;          // 0..127
            float4 vq = *(const float4*)(qbase + (size_t)row * DHEAD + d0 + d4 * 4);
            Qs[d4 * 4 + 0][row] = vq.x;
            Qs[d4 * 4 + 1][row] = vq.y;
            Qs[d4 * 4 + 2][row] = vq.z;
            Qs[d4 * 4 + 3][row] = vq.w;
            float4 vk = *(const float4*)(kbase + (size_t)row * DHEAD + d0 + d4 * 4);
            Ks[d4 * 4 + 0][row] = vk.x;
            Ks[d4 * 4 + 1][row] = vk.y;
            Ks[d4 * 4 + 2][row] = vk.z;
            Ks[d4 * 4 + 3][row] = vk.w;
        }
        __syncthreads();

#pragma unroll
        for (int kk = 0; kk < 32; kk++) {
            float a[8], bb[8];
            *(float4*)&a[0]  = *(const float4*)&Qs[kk][ty * 8];
            *(float4*)&a[4]  = *(const float4*)&Qs[kk][ty * 8 + 4];
            *(float4*)&bb[0] = *(const float4*)&Ks[kk][tx * 8];
            *(float4*)&bb[4] = *(const float4*)&Ks[kk][tx * 8 + 4];
#pragma unroll
            for (int i = 0; i < 8; i++)
#pragma unroll
                for (int j = 0; j < 8; j++)
                    acc[i][j] = fmaf(a[i], bb[j], acc[i][j]);
        }
        __syncthreads();
    }

    // Epilogue: scale, mask, exp, write E, accumulate per-row sums.
    const int mode = g_mask_mode;
    float rsum[8];
#pragma unroll
    for (int i = 0; i < 8; i++) {
        const int row = q0 + ty * 8 + i;
        const size_t roff = ((size_t)b * NQ + row) * NK + k0 + tx * 8;

        // Decode 8 mask flags at element offset roff, per storage mode.
        bool mk[8];
        if (mode == 1) {            // int32 0/1
            const uint4 ma = *(const uint4*)((const int*)mask + roff);
            const uint4 mb = *(const uint4*)((const int*)mask + roff + 4);
            mk[0] = ma.x != 0u; mk[1] = ma.y != 0u; mk[2] = ma.z != 0u; mk[3] = ma.w != 0u;
            mk[4] = mb.x != 0u; mk[5] = mb.y != 0u; mk[6] = mb.z != 0u; mk[7] = mb.w != 0u;
        } else if (mode == 0) {     // 1-byte bool
            const uint2 mm = *(const uint2*)((const unsigned char*)mask + roff);
#pragma unroll
            for (int j = 0; j < 4; j++) mk[j]     = ((mm.x >> (8 * j)) & 0xffu) != 0u;
#pragma unroll
            for (int j = 0; j < 4; j++) mk[4 + j] = ((mm.y >> (8 * j)) & 0xffu) != 0u;
        } else {                    // float32 0.0/1.0
            const float4 ma = *(const float4*)((const float*)mask + roff);
            const float4 mb = *(const float4*)((const float*)mask + roff + 4);
            mk[0] = ma.x != 0.0f; mk[1] = ma.y != 0.0f; mk[2] = ma.z != 0.0f; mk[3] = ma.w != 0.0f;
            mk[4] = mb.x != 0.0f; mk[5] = mb.y != 0.0f; mk[6] = mb.z != 0.0f; mk[7] = mb.w != 0.0f;
        }

        float e[8];
#pragma unroll
        for (int j = 0; j < 8; j++) {
            const float s = acc[i][j] * INV_SQRT_SCALE;
            e[j] = mk[j] ? 0.0f : __expf(s);
        }
        rsum[i] = ((e[0] + e[1]) + (e[2] + e[3])) + ((e[4] + e[5]) + (e[6] + e[7]));
        *(float4*)(att + roff)     = make_float4(e[0], e[1], e[2], e[3]);
        *(float4*)(att + roff + 4) = make_float4(e[4], e[5], e[6], e[7]);
    }

    // Reduce row sums across the 16 tx lanes (half-warp tree; lanes 0 / 16 end
    // up with the correct totals for their respective ty groups).
#pragma unroll
    for (int off = 8; off > 0; off >>= 1)
#pragma unroll
        for (int i = 0; i < 8; i++)
            rsum[i] += __shfl_down_sync(0xffffffffu, rsum[i], off);

    if (tx == 0) {
#pragma unroll
        for (int i = 0; i < 8; i++)
            g_partial[((size_t)b * NQ + q0 + ty * 8 + i) * KBLOCKS + blockIdx.x] = rsum[i];
    }
}

// ---------------------------------------------------------------------------
// Kernel 2: rd = 1/sum(partials); att *= rd (in place); context = att @ V.
// CTA tile: 128 q-rows x 128 dims (full D), loop over NK in chunks of 32.
// ---------------------------------------------------------------------------
__global__ __launch_bounds__(256) void av_kernel(
    const float* __restrict__ v,
    float* __restrict__ att,
    float* __restrict__ ctx)
{
    const int b  = blockIdx.y;
    const int q0 = blockIdx.x * 128;

    __shared__ __align__(16) float As[32][132];  // [kk][row], normalized att
    __shared__ __align__(16) float Vs[32][132];  // [kk][d]
    __shared__ float rd[128];

    const int tid = threadIdx.x;
    const int tx = tid & 15;
    const int ty = tid >> 4;

    if (tid < 128) {
        const float* p = &g_partial[((size_t)b * NQ + q0 + tid) * KBLOCKS];
        float s = 0.0f;
#pragma unroll
        for (int i = 0; i < KBLOCKS; i++) s += p[i];
        rd[tid] = 1.0f / s;
    }
    __syncthreads();

    float acc[8][8];
#pragma unroll
    for (int i = 0; i < 8; i++)
#pragma unroll
        for (int j = 0; j < 8; j++) acc[i][j] = 0.0f;

    float* attbase = att + ((size_t)b * NQ + q0) * NK;
    const float* vbase = v + (size_t)b * NK * DHEAD;

    for (int n0 = 0; n0 < NK; n0 += 32) {
#pragma unroll
        for (int it = 0; it < 4; it++) {
            const int li = it * 256 + tid;   // 0..1023
            // att chunk: 128 rows x 32 keys, normalize + write back + smem^T
            {
                const int k4  = li & 7;
                const int row = li >> 3;
                float* p = attbase + (size_t)row * NK + n0 + k4 * 4;
                float4 e = *(const float4*)p;
                const float r = rd[row];
                e.x *= r; e.y *= r; e.z *= r; e.w *= r;
                *(float4*)p = e;
                As[k4 * 4 + 0][row] = e.x;
                As[k4 * 4 + 1][row] = e.y;
                As[k4 * 4 + 2][row] = e.z;
                As[k4 * 4 + 3][row] = e.w;
            }
            // V chunk: 32 keys x 128 dims, natural layout
            {
                const int d4 = li & 31;
                const int vr = li >> 5;
                float4 vv = *(const float4*)(vbase + (size_t)(n0 + vr) * DHEAD + d4 * 4);
                *(float4*)&Vs[vr][d4 * 4] = vv;
            }
        }
        __syncthreads();

#pragma unroll
        for (int kk = 0; kk < 32; kk++) {
            float a[8], vv[8];
            *(float4*)&a[0]  = *(const float4*)&As[kk][ty * 8];
            *(float4*)&a[4]  = *(const float4*)&As[kk][ty * 8 + 4];
            *(float4*)&vv[0] = *(const float4*)&Vs[kk][tx * 8];
            *(float4*)&vv[4] = *(const float4*)&Vs[kk][tx * 8 + 4];
#pragma unroll
            for (int i = 0; i < 8; i++)
#pragma unroll
                for (int j = 0; j < 8; j++)
                    acc[i][j] = fmaf(a[i], vv[j], acc[i][j]);
        }
        __syncthreads();
    }

#pragma unroll
    for (int i = 0; i < 8; i++) {
        const int row = q0 + ty * 8 + i;
        float* o = ctx + ((size_t)b * NQ + row) * DHEAD + tx * 8;
        *(float4*)(o)     = make_float4(acc[i][0], acc[i][1], acc[i][2], acc[i][3]);
        *(float4*)(o + 4) = make_float4(acc[i][4], acc[i][5], acc[i][6], acc[i][7]);
    }
}

// ---------------------------------------------------------------------------
extern "C" void kernel_launch(void* const* d_in, const int* in_sizes, int n_in,
                              void* d_out, int out_size)
{
    const float* q = (const float*)d_in[0];
    const float* k = (const float*)d_in[1];
    const float* v = (const float*)d_in[2];
    const void*  mask = d_in[3];

    float* out = (float*)d_out;
    float* ctx = out;                                   // [B, NQ, D]
    float* att = out + (size_t)BATCH * NQ * DHEAD;      // [B, NQ, NK]

    detect_mask_kernel<<<1, 1>>>((const unsigned char*)mask);

    dim3 blk(256);
    dim3 g1(NK / 128, NQ / 128, BATCH);
    qk_exp_kernel<<<g1, blk>>>(q, k, mask, att);

    dim3 g2(NQ / 128, BATCH);
    av_kernel<<<g2, blk>>>(v, att, ctx);
}

// round 4
// speedup vs baseline: 1.3104x; 1.3104x over previous
#include <cuda_runtime.h>
#include <cuda_bf16.h>
#include <cstdint>

#define BATCH 16
#define NQ 2048
#define NK 2048
#define DHEAD 128
#define KBLOCKS 16
#define INV_SQRT_SCALE 0.08838834764831845f  // 1/sqrt(128)

// smem tile geometry: bf16 tiles 128 rows x 128 cols, padded stride 136 elems.
#define TSTRIDE 136
#define TBYTES (128 * TSTRIDE * 2)      // 34816
#define OFF_AH 0
#define OFF_AL TBYTES
#define OFF_BH (2 * TBYTES)
#define OFF_BL (3 * TBYTES)
#define SMEM_K1 (4 * TBYTES)            // 139264
#define SMEM_K2 (4 * TBYTES + 512)      // + rd[128]
#define SCSTRIDE 132                    // score/ctx staging stride (floats)

__device__ float g_partial[(size_t)BATCH * NQ * KBLOCKS];
__device__ int g_mask_mode;   // 0 = bytes, 1 = int32, 2 = float32

// ---------------------------------------------------------------------------
// Warp-MMA primitives (portable PTX, compile on base sm_103 target)
// ---------------------------------------------------------------------------
__device__ __forceinline__ uint32_t smem_u32(const void* p) {
    uint32_t a;
    asm("{ .reg .u64 t; cvta.to.shared.u64 t, %1; cvt.u32.u64 %0, t; }" : "=r"(a) : "l"(p));
    return a;
}
__device__ __forceinline__ void ldsm_x4(uint32_t a, uint32_t r[4]) {
    asm volatile("ldmatrix.sync.aligned.m8n8.x4.shared.b16 {%0,%1,%2,%3}, [%4];"
        : "=r"(r[0]), "=r"(r[1]), "=r"(r[2]), "=r"(r[3]) : "r"(a));
}
__device__ __forceinline__ void ldsm_x2(uint32_t a, uint32_t r[2]) {
    asm volatile("ldmatrix.sync.aligned.m8n8.x2.shared.b16 {%0,%1}, [%2];"
        : "=r"(r[0]), "=r"(r[1]) : "r"(a));
}
__device__ __forceinline__ void ldsm_x2t(uint32_t a, uint32_t r[2]) {
    asm volatile("ldmatrix.sync.aligned.m8n8.x2.trans.shared.b16 {%0,%1}, [%2];"
        : "=r"(r[0]), "=r"(r[1]) : "r"(a));
}
__device__ __forceinline__ void mma16816(float c[4], const uint32_t a[4], const uint32_t b[2]) {
    asm volatile("mma.sync.aligned.m16n8k16.row.col.f32.bf16.bf16.f32 "
        "{%0,%1,%2,%3}, {%4,%5,%6,%7}, {%8,%9}, {%0,%1,%2,%3};"
        : "+f"(c[0]), "+f"(c[1]), "+f"(c[2]), "+f"(c[3])
        : "r"(a[0]), "r"(a[1]), "r"(a[2]), "r"(a[3]), "r"(b[0]), "r"(b[1]));
}

__device__ __forceinline__ uint32_t pack2(__nv_bfloat16 a, __nv_bfloat16 b) {
    __nv_bfloat162 t = __halves2bfloat162(a, b);
    return *reinterpret_cast<uint32_t*>(&t);
}
__device__ __forceinline__ void split2(float x, float y, uint32_t& h, uint32_t& l) {
    __nv_bfloat16 hx = __float2bfloat16(x), hy = __float2bfloat16(y);
    __nv_bfloat16 lx = __float2bfloat16(x - __bfloat162float(hx));
    __nv_bfloat16 ly = __float2bfloat16(y - __bfloat162float(hy));
    h = pack2(hx, hy);
    l = pack2(lx, ly);
}

// Load a 128x128 f32 tile (row stride = srcStride) into hi/lo bf16 smem tiles.
__device__ __forceinline__ void load_split_tile(
    const float* __restrict__ src, size_t srcStride,
    char* smem, int offH, int offL, int tid)
{
#pragma unroll
    for (int it = 0; it < 16; it++) {
        const int idx = it * 256 + tid;     // 0..4095
        const int row = idx >> 5;
        const int c4  = idx & 31;
        const float4 v = *(const float4*)(src + (size_t)row * srcStride + c4 * 4);
        uint32_t h0, l0, h1, l1;
        split2(v.x, v.y, h0, l0);
        split2(v.z, v.w, h1, l1);
        const int off = row * (TSTRIDE * 2) + c4 * 8;
        *(uint2*)(smem + offH + off) = make_uint2(h0, h1);
        *(uint2*)(smem + offL + off) = make_uint2(l0, l1);
    }
}

// ---------------------------------------------------------------------------
__global__ void detect_mask_kernel(const unsigned char* __restrict__ m)
{
    const int tid = threadIdx.x;
    int mis = 0, ftail = 0;
    for (int i = tid * 16; i < tid * 16 + 16; i++) {
        const unsigned char b = m[i];
        if (b) {
            const int r = i & 3;
            if (r == 1) mis = 1;
            else if (r == 2) { if (b != 0x80) mis = 1; else ftail = 1; }
            else if (r == 3) { if (b != 0x3F) mis = 1; else ftail = 1; }
        }
    }
    const int anyMis = __syncthreads_or(mis);
    const int anyF   = __syncthreads_or(ftail);
    if (tid == 0) g_mask_mode = anyMis ? 0 : (anyF ? 2 : 1);
}

// ---------------------------------------------------------------------------
// Kernel 1: E = exp(mask ? -inf : QK^T * inv_sqrt_scale), unnormalized, plus
// per-(row, kblock) partial sums. 3-term bf16 split MMA (HH + HL + LH).
// ---------------------------------------------------------------------------
__global__ __launch_bounds__(256, 1)
void qk_exp_kernel(const float* __restrict__ q,
                   const float* __restrict__ k,
                   const void* __restrict__ mask,
                   float* __restrict__ att)
{
    extern __shared__ char smem[];
    const int tid = threadIdx.x;
    const int wid = tid >> 5;
    const int lane = tid & 31;

    const int b  = blockIdx.z;
    const int q0 = blockIdx.y * 128;
    const int k0 = blockIdx.x * 128;

    load_split_tile(q + ((size_t)b * NQ + q0) * DHEAD, DHEAD, smem, OFF_AH, OFF_AL, tid);
    load_split_tile(k + ((size_t)b * NK + k0) * DHEAD, DHEAD, smem, OFF_BH, OFF_BL, tid);
    __syncthreads();

    const int wm = wid & 1;     // 0/1 -> 64-row half
    const int wn = wid >> 1;    // 0..3 -> 32-col group
    const uint32_t sb = smem_u32(smem);

    float acc[4][4][4];
#pragma unroll
    for (int mt = 0; mt < 4; mt++)
#pragma unroll
        for (int nt = 0; nt < 4; nt++)
#pragma unroll
            for (int r = 0; r < 4; r++) acc[mt][nt][r] = 0.0f;

    const int lm = lane & 15, lq = lane >> 4;
    const int bn = lane & 7,  bk = (lane >> 3) & 1;

#pragma unroll
    for (int ks = 0; ks < 8; ks++) {
        const int kb = ks * 16;
        uint32_t ah[4][4], al[4][4], bh[4][2], bl[4][2];
#pragma unroll
        for (int mt = 0; mt < 4; mt++) {
            const uint32_t a = sb + OFF_AH + (wm * 64 + mt * 16 + lm) * (TSTRIDE * 2) + (kb + lq * 8) * 2;
            ldsm_x4(a, ah[mt]);
            ldsm_x4(a + TBYTES, al[mt]);
        }
#pragma unroll
        for (int nt = 0; nt < 4; nt++) {
            const uint32_t a = sb + OFF_BH + (wn * 32 + nt * 8 + bn) * (TSTRIDE * 2) + (kb + bk * 8) * 2;
            ldsm_x2(a, bh[nt]);
            ldsm_x2(a + TBYTES, bl[nt]);
        }
#pragma unroll
        for (int mt = 0; mt < 4; mt++)
#pragma unroll
            for (int nt = 0; nt < 4; nt++) {
                mma16816(acc[mt][nt], ah[mt], bh[nt]);
                mma16816(acc[mt][nt], ah[mt], bl[nt]);
                mma16816(acc[mt][nt], al[mt], bh[nt]);
            }
    }

    // Stage scores through smem for coalesced epilogue.
    __syncthreads();
    float* sc = (float*)smem;
    {
        const int r0 = lane >> 2;
        const int c0 = (lane & 3) * 2;
#pragma unroll
        for (int mt = 0; mt < 4; mt++)
#pragma unroll
            for (int nt = 0; nt < 4; nt++) {
                const int rr = wm * 64 + mt * 16 + r0;
                const int cc = wn * 32 + nt * 8 + c0;
                sc[rr * SCSTRIDE + cc]       = acc[mt][nt][0];
                sc[rr * SCSTRIDE + cc + 1]   = acc[mt][nt][1];
                sc[(rr + 8) * SCSTRIDE + cc]     = acc[mt][nt][2];
                sc[(rr + 8) * SCSTRIDE + cc + 1] = acc[mt][nt][3];
            }
    }
    __syncthreads();

    // Epilogue: two threads per row (64 cols each), coalesced.
    {
        const int row  = tid & 127;
        const int half = tid >> 7;
        const int mode = g_mask_mode;
        const size_t roff = ((size_t)b * NQ + q0 + row) * NK + k0 + half * 64;
        float rsum = 0.0f;
#pragma unroll
        for (int j = 0; j < 16; j++) {
            const float4 s4 = *(const float4*)&sc[row * SCSTRIDE + half * 64 + j * 4];
            bool mk[4];
            if (mode == 1) {
                const uint4 mm = *(const uint4*)((const int*)mask + roff + j * 4);
                mk[0] = mm.x != 0u; mk[1] = mm.y != 0u; mk[2] = mm.z != 0u; mk[3] = mm.w != 0u;
            } else if (mode == 0) {
                const uint32_t mm = *(const uint32_t*)((const unsigned char*)mask + roff + j * 4);
#pragma unroll
                for (int jj = 0; jj < 4; jj++) mk[jj] = ((mm >> (8 * jj)) & 0xffu) != 0u;
            } else {
                const float4 mm = *(const float4*)((const float*)mask + roff + j * 4);
                mk[0] = mm.x != 0.0f; mk[1] = mm.y != 0.0f; mk[2] = mm.z != 0.0f; mk[3] = mm.w != 0.0f;
            }
            float e[4];
            const float ss[4] = {s4.x, s4.y, s4.z, s4.w};
#pragma unroll
            for (int jj = 0; jj < 4; jj++)
                e[jj] = mk[jj] ? 0.0f : __expf(ss[jj] * INV_SQRT_SCALE);
            rsum += (e[0] + e[1]) + (e[2] + e[3]);
            *(float4*)(att + roff + j * 4) = make_float4(e[0], e[1], e[2], e[3]);
        }
        sc[row * SCSTRIDE + 128 + half] = rsum;   // pad columns hold partials
    }
    __syncthreads();
    if (tid < 128)
        g_partial[((size_t)b * NQ + q0 + tid) * KBLOCKS + blockIdx.x] =
            sc[tid * SCSTRIDE + 128] + sc[tid * SCSTRIDE + 129];
}

// ---------------------------------------------------------------------------
// Kernel 2: normalize att in place; ctx = att @ V (3-term bf16 split MMA).
// ---------------------------------------------------------------------------
__global__ __launch_bounds__(256, 1)
void av_kernel(const float* __restrict__ v,
               float* __restrict__ att,
               float* __restrict__ ctx)
{
    extern __shared__ char smem[];
    float* rd = (float*)(smem + 4 * TBYTES);
    const int tid = threadIdx.x;
    const int wid = tid >> 5;
    const int lane = tid & 31;

    const int b  = blockIdx.y;
    const int q0 = blockIdx.x * 128;

    if (tid < 128) {
        const float* p = &g_partial[((size_t)b * NQ + q0 + tid) * KBLOCKS];
        float s = 0.0f;
#pragma unroll
        for (int i = 0; i < KBLOCKS; i++) s += p[i];
        rd[tid] = 1.0f / s;
    }
    __syncthreads();

    const int wm = wid & 1;
    const int wn = wid >> 1;
    const uint32_t sb = smem_u32(smem);

    float acc[4][4][4];
#pragma unroll
    for (int mt = 0; mt < 4; mt++)
#pragma unroll
        for (int nt = 0; nt < 4; nt++)
#pragma unroll
            for (int r = 0; r < 4; r++) acc[mt][nt][r] = 0.0f;

    float* attbase = att + ((size_t)b * NQ + q0) * NK;
    const float* vbase = v + (size_t)b * NK * DHEAD;

    const int lm = lane & 15, lq = lane >> 4;
    const int lk = lane & 15;

    for (int it = 0; it < NK / 128; it++) {
        const int n0 = it * 128;
        // att chunk: normalize, write back, split into A tiles.
#pragma unroll
        for (int l = 0; l < 16; l++) {
            const int idx = l * 256 + tid;
            const int row = idx >> 5;
            const int c4  = idx & 31;
            float* p = attbase + (size_t)row * NK + n0 + c4 * 4;
            float4 e = *(const float4*)p;
            const float r = rd[row];
            e.x *= r; e.y *= r; e.z *= r; e.w *= r;
            *(float4*)p = e;
            uint32_t h0, l0, h1, l1;
            split2(e.x, e.y, h0, l0);
            split2(e.z, e.w, h1, l1);
            const int off = row * (TSTRIDE * 2) + c4 * 8;
            *(uint2*)(smem + OFF_AH + off) = make_uint2(h0, h1);
            *(uint2*)(smem + OFF_AL + off) = make_uint2(l0, l1);
        }
        // V chunk [k][d] natural layout, split into B tiles.
        load_split_tile(vbase + (size_t)n0 * DHEAD, DHEAD, smem, OFF_BH, OFF_BL, tid);
        __syncthreads();

#pragma unroll
        for (int ks = 0; ks < 8; ks++) {
            const int kb = ks * 16;
            uint32_t ah[4][4], al[4][4], bh[4][2], bl[4][2];
#pragma unroll
            for (int mt = 0; mt < 4; mt++) {
                const uint32_t a = sb + OFF_AH + (wm * 64 + mt * 16 + lm) * (TSTRIDE * 2) + (kb + lq * 8) * 2;
                ldsm_x4(a, ah[mt]);
                ldsm_x4(a + TBYTES, al[mt]);
            }
#pragma unroll
            for (int nt = 0; nt < 4; nt++) {
                const uint32_t a = sb + OFF_BH + (kb + lk) * (TSTRIDE * 2) + (wn * 32 + nt * 8) * 2;
                ldsm_x2t(a, bh[nt]);
                ldsm_x2t(a + TBYTES, bl[nt]);
            }
#pragma unroll
            for (int mt = 0; mt < 4; mt++)
#pragma unroll
                for (int nt = 0; nt < 4; nt++) {
                    mma16816(acc[mt][nt], ah[mt], bh[nt]);
                    mma16816(acc[mt][nt], ah[mt], bl[nt]);
                    mma16816(acc[mt][nt], al[mt], bh[nt]);
                }
        }
        __syncthreads();
    }

    // Stage ctx through smem for coalesced writes.
    float* sc = (float*)smem;
    {
        const int r0 = lane >> 2;
        const int c0 = (lane & 3) * 2;
#pragma unroll
        for (int mt = 0; mt < 4; mt++)
#pragma unroll
            for (int nt = 0; nt < 4; nt++) {
                const int rr = wm * 64 + mt * 16 + r0;
                const int cc = wn * 32 + nt * 8 + c0;
                sc[rr * SCSTRIDE + cc]       = acc[mt][nt][0];
                sc[rr * SCSTRIDE + cc + 1]   = acc[mt][nt][1];
                sc[(rr + 8) * SCSTRIDE + cc]     = acc[mt][nt][2];
                sc[(rr + 8) * SCSTRIDE + cc + 1] = acc[mt][nt][3];
            }
    }
    __syncthreads();
    {
        const int row  = tid & 127;
        const int half = tid >> 7;
        float* o = ctx + ((size_t)b * NQ + q0 + row) * DHEAD + half * 64;
#pragma unroll
        for (int j = 0; j < 16; j++)
            *(float4*)(o + j * 4) = *(const float4*)&sc[row * SCSTRIDE + half * 64 + j * 4];
    }
}

// ---------------------------------------------------------------------------
extern "C" void kernel_launch(void* const* d_in, const int* in_sizes, int n_in,
                              void* d_out, int out_size)
{
    const float* q = (const float*)d_in[0];
    const float* k = (const float*)d_in[1];
    const float* v = (const float*)d_in[2];
    const void*  mask = d_in[3];

    float* out = (float*)d_out;
    float* ctx = out;                                   // [B, NQ, D]
    float* att = out + (size_t)BATCH * NQ * DHEAD;      // [B, NQ, NK]

    cudaFuncSetAttribute(qk_exp_kernel, cudaFuncAttributeMaxDynamicSharedMemorySize, SMEM_K1);
    cudaFuncSetAttribute(av_kernel,     cudaFuncAttributeMaxDynamicSharedMemorySize, SMEM_K2);

    detect_mask_kernel<<<1, 256>>>((const unsigned char*)mask);

    dim3 g1(NK / 128, NQ / 128, BATCH);
    qk_exp_kernel<<<g1, 256, SMEM_K1>>>(q, k, mask, att);

    dim3 g2(NQ / 128, BATCH);
    av_kernel<<<g2, 256, SMEM_K2>>>(v, att, ctx);
}